// round 2
// baseline (speedup 1.0000x reference)
#include <cuda_runtime.h>
#include <math.h>

#define NB      4
#define IN_CHAN 128
#define HW      3136
#define HWP     3328      // padded to 13*256
#define OC      32
#define QC      8
#define D       16        // reduced score dim and value dim
#define JSPLIT  14
#define JLEN    (HW / JSPLIT)   // 224
#define TJ      32
#define BN_EPS  1e-5f

typedef unsigned long long ull;

// ---------------- packed f32x2 helpers (sm_10x dual-fp32 pipe) ----------------
__device__ __forceinline__ ull fma2(ull a, ull b, ull c) {
    ull d; asm("fma.rn.f32x2 %0, %1, %2, %3;" : "=l"(d) : "l"(a), "l"(b), "l"(c));
    return d;
}
__device__ __forceinline__ ull add2(ull a, ull b) {
    ull d; asm("add.rn.f32x2 %0, %1, %2;" : "=l"(d) : "l"(a), "l"(b));
    return d;
}
__device__ __forceinline__ float2 unpack2(ull a) {
    float2 f; asm("mov.b64 {%0, %1}, %2;" : "=f"(f.x), "=f"(f.y) : "l"(a));
    return f;
}
__device__ __forceinline__ ull pack2(float lo, float hi) {
    ull r; asm("mov.b64 %0, {%1, %2};" : "=l"(r) : "f"(lo), "f"(hi));
    return r;
}

// ---------------- scratch (device globals; no allocation allowed) ----------------
__device__ __align__(16) float g_A[NB][HWP][D];                 // [q + rk ; rq]
__device__ __align__(16) float g_B[NB][HWP][D];                 // [k ; q]
__device__ __align__(16) float g_V[NB][HWP][D];                 // v + rv
__device__ __align__(16) float g_pacc[JSPLIT][NB][HWP][D];      // partial sum(e^s * v)
__device__ __align__(16) float g_pl[JSPLIT][NB][HWP];           // partial sum(e^s)

// ======================================================================
// Kernel 1: QKV 1x1 conv + BN + build A/B/Vext.
// 4 warps x 8 output-channels each, 32 pixels per block -> grid 416.
// Phase 2: 4 segment groups regroup q/k/v via smem into A/B/V rows.
// ======================================================================
__global__ __launch_bounds__(128)
void qkv_kernel(const float* __restrict__ x, const float* __restrict__ w,
                const float* __restrict__ bq, const float* __restrict__ gamma,
                const float* __restrict__ beta, const float* __restrict__ mean,
                const float* __restrict__ var,
                const float* __restrict__ rq, const float* __restrict__ rk,
                const float* __restrict__ rv)
{
    __shared__ float sw[IN_CHAN][OC];     // transposed weights [c][o]
    __shared__ float sscale[OC], sbias[OC];
    __shared__ float sr[32][OC + 1];      // post-BN qkv per pixel (padded)

    const int tid  = threadIdx.x;
    const int warp = tid >> 5;
    const int lane = tid & 31;

    for (int idx = tid; idx < IN_CHAN * OC; idx += 128) {
        int o = idx & (OC - 1), c = idx >> 5;
        sw[c][o] = w[o * IN_CHAN + c];
    }
    if (tid < OC) {
        float sc = gamma[tid] * rsqrtf(var[tid] + BN_EPS);
        sscale[tid] = sc;
        sbias[tid]  = (bq[tid] - mean[tid]) * sc + beta[tid];
    }
    __syncthreads();

    const int n     = blockIdx.y;
    const int pix   = blockIdx.x * 32 + lane;
    const int obase = warp * 8;

    if (pix < HW) {
        float acc[8];
        #pragma unroll
        for (int k = 0; k < 8; k++) acc[k] = 0.f;

        const float* xp = x + (size_t)n * IN_CHAN * HW + pix;
        #pragma unroll 4
        for (int c = 0; c < IN_CHAN; c++) {
            float xv = __ldg(xp + (size_t)c * HW);
            float4 wa = *reinterpret_cast<const float4*>(&sw[c][obase]);
            float4 wb = *reinterpret_cast<const float4*>(&sw[c][obase + 4]);
            acc[0] = fmaf(xv, wa.x, acc[0]);
            acc[1] = fmaf(xv, wa.y, acc[1]);
            acc[2] = fmaf(xv, wa.z, acc[2]);
            acc[3] = fmaf(xv, wa.w, acc[3]);
            acc[4] = fmaf(xv, wb.x, acc[4]);
            acc[5] = fmaf(xv, wb.y, acc[5]);
            acc[6] = fmaf(xv, wb.z, acc[6]);
            acc[7] = fmaf(xv, wb.w, acc[7]);
        }
        #pragma unroll
        for (int k = 0; k < 8; k++)
            sr[lane][obase + k] = fmaf(acc[k], sscale[obase + k], sbias[obase + k]);
    }
    __syncthreads();

    // Phase 2: build A/B/V rows. seg = warp id.
    const int p    = lane;
    const int gpix = blockIdx.x * 32 + p;
    const int seg  = warp;

    if (gpix < HW) {
        if (seg == 0) {               // A[0..7] = q + rk
            float av[8];
            #pragma unroll
            for (int c = 0; c < 8; c++)
                av[c] = sr[p][c] + __ldg(rk + (size_t)c * HW + gpix);
            reinterpret_cast<float4*>(&g_A[n][gpix][0])[0] = reinterpret_cast<float4*>(av)[0];
            reinterpret_cast<float4*>(&g_A[n][gpix][0])[1] = reinterpret_cast<float4*>(av)[1];
        } else if (seg == 1) {        // A[8..15] = rq
            float av[8];
            #pragma unroll
            for (int c = 0; c < 8; c++)
                av[c] = __ldg(rq + (size_t)c * HW + gpix);
            reinterpret_cast<float4*>(&g_A[n][gpix][8])[0] = reinterpret_cast<float4*>(av)[0];
            reinterpret_cast<float4*>(&g_A[n][gpix][8])[1] = reinterpret_cast<float4*>(av)[1];
        } else if (seg == 2) {        // B = [k ; q]
            float bv[16];
            #pragma unroll
            for (int c = 0; c < 8; c++) { bv[c] = sr[p][QC + c]; bv[QC + c] = sr[p][c]; }
            #pragma unroll
            for (int q4 = 0; q4 < 4; q4++)
                reinterpret_cast<float4*>(&g_B[n][gpix][0])[q4] = reinterpret_cast<float4*>(bv)[q4];
        } else {                      // V = v + rv
            float vv[16];
            #pragma unroll
            for (int c = 0; c < 16; c++)
                vv[c] = sr[p][2 * QC + c] + __ldg(rv + (size_t)c * HW + gpix);
            #pragma unroll
            for (int q4 = 0; q4 < 4; q4++)
                reinterpret_cast<float4*>(&g_V[n][gpix][0])[q4] = reinterpret_cast<float4*>(vv)[q4];
        }
    } else {
        // zero padded rows
        float4 z = make_float4(0.f, 0.f, 0.f, 0.f);
        if (seg == 0) {
            reinterpret_cast<float4*>(&g_A[n][gpix][0])[0] = z;
            reinterpret_cast<float4*>(&g_A[n][gpix][0])[1] = z;
        } else if (seg == 1) {
            reinterpret_cast<float4*>(&g_A[n][gpix][8])[0] = z;
            reinterpret_cast<float4*>(&g_A[n][gpix][8])[1] = z;
        } else if (seg == 2) {
            #pragma unroll
            for (int q4 = 0; q4 < 4; q4++)
                reinterpret_cast<float4*>(&g_B[n][gpix][0])[q4] = z;
        } else {
            #pragma unroll
            for (int q4 = 0; q4 < 4; q4++)
                reinterpret_cast<float4*>(&g_V[n][gpix][0])[q4] = z;
        }
    }
}

// ======================================================================
// Kernel 2: attention core with packed f32x2 FMA.
// No-max softmax (scores bounded << 88): j-split partials add linearly.
// grid: (13, JSPLIT, NB), block 128; each thread owns 2 queries.
// ======================================================================
__global__ __launch_bounds__(128)
void attn_kernel()
{
    __shared__ __align__(16) float sB[TJ * D];
    __shared__ __align__(16) float sV[TJ * D];

    const int tid   = threadIdx.x;
    const int itile = blockIdx.x;
    const int js    = blockIdx.y;
    const int n     = blockIdx.z;

    const int i0 = itile * 256 + tid;
    const int i1 = i0 + 128;

    // A rows as packed f32x2 pairs (adjacent d's are contiguous in memory)
    ull A0[8], A1[8];
    {
        const ulonglong2* a0p = reinterpret_cast<const ulonglong2*>(&g_A[n][i0][0]);
        const ulonglong2* a1p = reinterpret_cast<const ulonglong2*>(&g_A[n][i1][0]);
        #pragma unroll
        for (int q = 0; q < 4; q++) {
            ulonglong2 t0 = a0p[q]; A0[2 * q] = t0.x; A0[2 * q + 1] = t0.y;
            ulonglong2 t1 = a1p[q]; A1[2 * q] = t1.x; A1[2 * q + 1] = t1.y;
        }
    }

    ull acc0[8], acc1[8];
    #pragma unroll
    for (int k = 0; k < 8; k++) { acc0[k] = 0ull; acc1[k] = 0ull; }
    float l0 = 0.f, l1 = 0.f;

    const int jbase = js * JLEN;
    for (int t = 0; t < JLEN / TJ; t++) {
        const int j0 = jbase + t * TJ;
        reinterpret_cast<float4*>(sB)[tid] =
            reinterpret_cast<const float4*>(&g_B[n][j0][0])[tid];
        reinterpret_cast<float4*>(sV)[tid] =
            reinterpret_cast<const float4*>(&g_V[n][j0][0])[tid];
        __syncthreads();

        #pragma unroll 2
        for (int jj = 0; jj < TJ; jj++) {
            const ull* b = reinterpret_cast<const ull*>(&sB[jj * D]);
            ull s0a = 0ull, s0b = 0ull, s1a = 0ull, s1b = 0ull;
            #pragma unroll
            for (int k = 0; k < 4; k++) {
                s0a = fma2(A0[2 * k],     b[2 * k],     s0a);
                s0b = fma2(A0[2 * k + 1], b[2 * k + 1], s0b);
                s1a = fma2(A1[2 * k],     b[2 * k],     s1a);
                s1b = fma2(A1[2 * k + 1], b[2 * k + 1], s1b);
            }
            float2 u0 = unpack2(add2(s0a, s0b));
            float2 u1 = unpack2(add2(s1a, s1b));
            float p0 = __expf(u0.x + u0.y);
            float p1 = __expf(u1.x + u1.y);
            l0 += p0; l1 += p1;
            ull P0 = pack2(p0, p0);
            ull P1 = pack2(p1, p1);
            const ull* v = reinterpret_cast<const ull*>(&sV[jj * D]);
            #pragma unroll
            for (int k = 0; k < 8; k++) {
                acc0[k] = fma2(P0, v[k], acc0[k]);
                acc1[k] = fma2(P1, v[k], acc1[k]);
            }
        }
        __syncthreads();
    }

    // acc bit-layout == 16 contiguous floats; store directly
    {
        ulonglong2* o0 = reinterpret_cast<ulonglong2*>(&g_pacc[js][n][i0][0]);
        ulonglong2* o1 = reinterpret_cast<ulonglong2*>(&g_pacc[js][n][i1][0]);
        #pragma unroll
        for (int q = 0; q < 4; q++) {
            ulonglong2 t0; t0.x = acc0[2 * q]; t0.y = acc0[2 * q + 1]; o0[q] = t0;
            ulonglong2 t1; t1.x = acc1[2 * q]; t1.y = acc1[2 * q + 1]; o1[q] = t1;
        }
    }
    g_pl[js][n][i0] = l0;
    g_pl[js][n][i1] = l1;
}

// ======================================================================
// Kernel 3: combine j-split partials, normalize, 2x2 avg pool.
// ======================================================================
__global__ void combine_kernel(float* __restrict__ out)
{
    const int idx = blockIdx.x * blockDim.x + threadIdx.x;
    const int TOT = NB * 2 * QC * 28 * 28;
    if (idx >= TOT) return;
    int pw = idx % 28;
    int t  = idx / 28;
    int ph = t % 28; t /= 28;
    int c  = t % (2 * QC);
    int n  = t / (2 * QC);

    float r = 0.f;
    #pragma unroll
    for (int sh = 0; sh < 2; sh++) {
        #pragma unroll
        for (int sw_ = 0; sw_ < 2; sw_++) {
            int i = (2 * ph + sh) * 56 + (2 * pw + sw_);
            float num = 0.f, den = 0.f;
            #pragma unroll
            for (int s = 0; s < JSPLIT; s++) {
                num += g_pacc[s][n][i][c];
                den += g_pl[s][n][i];
            }
            r += num / den;
        }
    }
    out[idx] = 0.25f * r;
}

// ======================================================================
extern "C" void kernel_launch(void* const* d_in, const int* in_sizes, int n_in,
                              void* d_out, int out_size)
{
    const float* x     = (const float*)d_in[0];
    const float* w     = (const float*)d_in[1];
    const float* bq    = (const float*)d_in[2];
    const float* gamma = (const float*)d_in[3];
    const float* beta  = (const float*)d_in[4];
    const float* mean  = (const float*)d_in[5];
    const float* var   = (const float*)d_in[6];
    const float* rq    = (const float*)d_in[7];
    const float* rk    = (const float*)d_in[8];
    const float* rv    = (const float*)d_in[9];
    float* out = (float*)d_out;

    dim3 g1(HWP / 32, NB);
    qkv_kernel<<<g1, 128>>>(x, w, bq, gamma, beta, mean, var, rq, rk, rv);

    dim3 g2(HWP / 256, JSPLIT, NB);
    attn_kernel<<<g2, 128>>>();

    const int TOT = NB * 2 * QC * 28 * 28;
    combine_kernel<<<(TOT + 255) / 256, 256>>>(out);
}

// round 3
// speedup vs baseline: 1.1501x; 1.1501x over previous
#include <cuda_runtime.h>
#include <math.h>

#define NB      4
#define IN_CHAN 128
#define HW      3136
#define HWP     3328      // padded to 13*256
#define OC      32
#define QC      8
#define D       16        // reduced score dim and value dim
#define JSPLIT  14
#define JLEN    (HW / JSPLIT)   // 224
#define TJ      32
#define BN_EPS  1e-5f

// ---------------- scratch (device globals; no allocation allowed) ----------------
__device__ __align__(16) float g_A[NB][HWP][D];                 // [q + rk ; rq]
__device__ __align__(16) float g_B[NB][HWP][D];                 // [k ; q]
__device__ __align__(16) float g_V[NB][HWP][D];                 // v + rv
__device__ __align__(16) float g_pacc[JSPLIT][NB][HWP][D];      // partial sum(e^s * v)
__device__ __align__(16) float g_pl[JSPLIT][NB][HWP];           // partial sum(e^s)

// ======================================================================
// Kernel 1: QKV 1x1 conv + BN fold + build A/B/Vext.
// Latency fix: double-buffered batches of 16 independent LDGs (MLP=16)
// so the 6.4MB DRAM stream is latency-hidden by the 16x32 FMA block.
// grid: (HWP/128, NB), block: 128, one pixel per thread.
// ======================================================================
__global__ __launch_bounds__(128)
void qkv_kernel(const float* __restrict__ x, const float* __restrict__ w,
                const float* __restrict__ bq, const float* __restrict__ gamma,
                const float* __restrict__ beta, const float* __restrict__ mean,
                const float* __restrict__ var,
                const float* __restrict__ rq, const float* __restrict__ rk,
                const float* __restrict__ rv)
{
    __shared__ float sw[IN_CHAN][OC];     // transposed weights [c][o]
    __shared__ float sscale[OC], sbias[OC];

    const int tid = threadIdx.x;
    for (int idx = tid; idx < IN_CHAN * OC; idx += 128) {
        int o = idx & (OC - 1), c = idx >> 5;
        sw[c][o] = w[o * IN_CHAN + c];
    }
    if (tid < OC) {
        float sc = gamma[tid] * rsqrtf(var[tid] + BN_EPS);
        sscale[tid] = sc;
        sbias[tid]  = (bq[tid] - mean[tid]) * sc + beta[tid];
    }
    __syncthreads();

    const int n   = blockIdx.y;
    const int pix = blockIdx.x * 128 + tid;

    float* Ap = &g_A[n][pix][0];
    float* Bp = &g_B[n][pix][0];
    float* Vp = &g_V[n][pix][0];

    if (pix >= HW) {
        float4 z = make_float4(0.f, 0.f, 0.f, 0.f);
        #pragma unroll
        for (int q4 = 0; q4 < 4; q4++) {
            reinterpret_cast<float4*>(Ap)[q4] = z;
            reinterpret_cast<float4*>(Bp)[q4] = z;
            reinterpret_cast<float4*>(Vp)[q4] = z;
        }
        return;
    }

    float acc[OC];
    #pragma unroll
    for (int o = 0; o < OC; o++) acc[o] = 0.f;

    const float* xp = x + (size_t)n * IN_CHAN * HW + pix;

    // double-buffered 16-wide load batches
    float xv[2][16];
    #pragma unroll
    for (int u = 0; u < 16; u++)
        xv[0][u] = __ldg(xp + (size_t)u * HW);

    #pragma unroll
    for (int cb = 0; cb < IN_CHAN; cb += 16) {
        const int cur = (cb >> 4) & 1;
        if (cb + 16 < IN_CHAN) {
            #pragma unroll
            for (int u = 0; u < 16; u++)
                xv[1 - cur][u] = __ldg(xp + (size_t)(cb + 16 + u) * HW);
        }
        #pragma unroll
        for (int u = 0; u < 16; u++) {
            const float xs = xv[cur][u];
            #pragma unroll
            for (int o = 0; o < OC; o++)
                acc[o] = fmaf(xs, sw[cb + u][o], acc[o]);
        }
    }

    float r[OC];
    #pragma unroll
    for (int o = 0; o < OC; o++) r[o] = fmaf(acc[o], sscale[o], sbias[o]);

    // A = [q + rk_col ; rq_col],  B = [k ; q],  V = v + rv
    float av[D], bv[D], vv[D];
    #pragma unroll
    for (int c = 0; c < QC; c++) {
        av[c]      = r[c] + __ldg(rk + (size_t)c * HW + pix);
        av[QC + c] = __ldg(rq + (size_t)c * HW + pix);
        bv[c]      = r[QC + c];
        bv[QC + c] = r[c];
    }
    #pragma unroll
    for (int c = 0; c < 2 * QC; c++)
        vv[c] = r[2 * QC + c] + __ldg(rv + (size_t)c * HW + pix);

    #pragma unroll
    for (int q4 = 0; q4 < 4; q4++) {
        reinterpret_cast<float4*>(Ap)[q4] = reinterpret_cast<float4*>(av)[q4];
        reinterpret_cast<float4*>(Bp)[q4] = reinterpret_cast<float4*>(bv)[q4];
        reinterpret_cast<float4*>(Vp)[q4] = reinterpret_cast<float4*>(vv)[q4];
    }
}

// ======================================================================
// Kernel 2: attention core (R1 scalar version — at fp32 FFMA roofline).
// No-max softmax (scores bounded << 88): j-split partials add linearly.
// grid: (13, JSPLIT, NB), block 128; each thread owns 2 queries.
// ======================================================================
__global__ __launch_bounds__(128)
void attn_kernel()
{
    __shared__ __align__(16) float sB[TJ * D];
    __shared__ __align__(16) float sV[TJ * D];

    const int tid   = threadIdx.x;
    const int itile = blockIdx.x;
    const int js    = blockIdx.y;
    const int n     = blockIdx.z;

    const int i0 = itile * 256 + tid;
    const int i1 = i0 + 128;

    float a0[D], a1[D];
    #pragma unroll
    for (int q4 = 0; q4 < 4; q4++) {
        reinterpret_cast<float4*>(a0)[q4] =
            reinterpret_cast<const float4*>(&g_A[n][i0][0])[q4];
        reinterpret_cast<float4*>(a1)[q4] =
            reinterpret_cast<const float4*>(&g_A[n][i1][0])[q4];
    }

    float acc0[D], acc1[D];
    #pragma unroll
    for (int d = 0; d < D; d++) { acc0[d] = 0.f; acc1[d] = 0.f; }
    float l0 = 0.f, l1 = 0.f;

    const int jbase = js * JLEN;
    for (int t = 0; t < JLEN / TJ; t++) {
        const int j0 = jbase + t * TJ;
        reinterpret_cast<float4*>(sB)[tid] =
            reinterpret_cast<const float4*>(&g_B[n][j0][0])[tid];
        reinterpret_cast<float4*>(sV)[tid] =
            reinterpret_cast<const float4*>(&g_V[n][j0][0])[tid];
        __syncthreads();

        #pragma unroll 2
        for (int jj = 0; jj < TJ; jj++) {
            const float* b = &sB[jj * D];
            float s0a = 0.f, s0b = 0.f, s1a = 0.f, s1b = 0.f;
            #pragma unroll
            for (int d = 0; d < D; d += 2) {
                s0a = fmaf(a0[d],     b[d],     s0a);
                s0b = fmaf(a0[d + 1], b[d + 1], s0b);
                s1a = fmaf(a1[d],     b[d],     s1a);
                s1b = fmaf(a1[d + 1], b[d + 1], s1b);
            }
            float p0 = __expf(s0a + s0b);
            float p1 = __expf(s1a + s1b);
            l0 += p0; l1 += p1;
            const float* v = &sV[jj * D];
            #pragma unroll
            for (int d = 0; d < D; d++) {
                acc0[d] = fmaf(p0, v[d], acc0[d]);
                acc1[d] = fmaf(p1, v[d], acc1[d]);
            }
        }
        __syncthreads();
    }

    #pragma unroll
    for (int q4 = 0; q4 < 4; q4++) {
        reinterpret_cast<float4*>(&g_pacc[js][n][i0][0])[q4] =
            reinterpret_cast<float4*>(acc0)[q4];
        reinterpret_cast<float4*>(&g_pacc[js][n][i1][0])[q4] =
            reinterpret_cast<float4*>(acc1)[q4];
    }
    g_pl[js][n][i0] = l0;
    g_pl[js][n][i1] = l1;
}

// ======================================================================
// Kernel 3: combine j-split partials, normalize, 2x2 avg pool.
// ======================================================================
__global__ void combine_kernel(float* __restrict__ out)
{
    const int idx = blockIdx.x * blockDim.x + threadIdx.x;
    const int TOT = NB * 2 * QC * 28 * 28;
    if (idx >= TOT) return;
    int pw = idx % 28;
    int t  = idx / 28;
    int ph = t % 28; t /= 28;
    int c  = t % (2 * QC);
    int n  = t / (2 * QC);

    float r = 0.f;
    #pragma unroll
    for (int sh = 0; sh < 2; sh++) {
        #pragma unroll
        for (int sw_ = 0; sw_ < 2; sw_++) {
            int i = (2 * ph + sh) * 56 + (2 * pw + sw_);
            float num = 0.f, den = 0.f;
            #pragma unroll
            for (int s = 0; s < JSPLIT; s++) {
                num += g_pacc[s][n][i][c];
                den += g_pl[s][n][i];
            }
            r += num / den;
        }
    }
    out[idx] = 0.25f * r;
}

// ======================================================================
extern "C" void kernel_launch(void* const* d_in, const int* in_sizes, int n_in,
                              void* d_out, int out_size)
{
    const float* x     = (const float*)d_in[0];
    const float* w     = (const float*)d_in[1];
    const float* bq    = (const float*)d_in[2];
    const float* gamma = (const float*)d_in[3];
    const float* beta  = (const float*)d_in[4];
    const float* mean  = (const float*)d_in[5];
    const float* var   = (const float*)d_in[6];
    const float* rq    = (const float*)d_in[7];
    const float* rk    = (const float*)d_in[8];
    const float* rv    = (const float*)d_in[9];
    float* out = (float*)d_out;

    dim3 g1(HWP / 128, NB);
    qkv_kernel<<<g1, 128>>>(x, w, bq, gamma, beta, mean, var, rq, rk, rv);

    dim3 g2(HWP / 256, JSPLIT, NB);
    attn_kernel<<<g2, 128>>>();

    const int TOT = NB * 2 * QC * 28 * 28;
    combine_kernel<<<(TOT + 255) / 256, 256>>>(out);
}

// round 4
// speedup vs baseline: 1.1561x; 1.0052x over previous
#include <cuda_runtime.h>
#include <math.h>

#define NB      4
#define IN_CHAN 128
#define HW      3136
#define HWP     3328      // padded to 13*256 (and 52*64)
#define OC      32
#define QC      8
#define D       16        // reduced score dim and value dim
#define JSPLIT  14
#define JLEN    (HW / JSPLIT)   // 224
#define TJ      32
#define BN_EPS  1e-5f
#define QPIX    64        // pixels per qkv block

// ---------------- scratch (device globals; no allocation allowed) ----------------
__device__ __align__(16) float g_A[NB][HWP][D];                 // [q + rk ; rq]
__device__ __align__(16) float g_B[NB][HWP][D];                 // [k ; q]
__device__ __align__(16) float g_V[NB][HWP][D];                 // v + rv
__device__ __align__(16) float g_pacc[JSPLIT][NB][HWP][D];      // partial sum(e^s * v)
__device__ __align__(16) float g_pl[JSPLIT][NB][HWP];           // partial sum(e^s)

// ======================================================================
// Kernel 1: QKV 1x1 conv + BN + build A/B/Vext.
// Latency hiding via WARP COUNT: 256 threads per 64 pixels, 4-way
// channel split (32 LDG / 1024 FMA per thread), smem tree reduction,
// segmented epilogue. grid = (52, NB) = 208 blocks x 8 warps.
// ======================================================================
__global__ __launch_bounds__(256)
void qkv_kernel(const float* __restrict__ x, const float* __restrict__ w,
                const float* __restrict__ bq, const float* __restrict__ gamma,
                const float* __restrict__ beta, const float* __restrict__ mean,
                const float* __restrict__ var,
                const float* __restrict__ rq, const float* __restrict__ rk,
                const float* __restrict__ rv)
{
    __shared__ float sw[IN_CHAN][OC];            // 16 KB transposed weights
    __shared__ float sscale[OC], sbias[OC];
    __shared__ float sacc[2][QPIX][OC + 1];      // 16.9 KB reduction buffers
    __shared__ float sr[QPIX][OC + 1];           // 8.4 KB post-BN qkv

    const int tid = threadIdx.x;
    const int p   = tid & (QPIX - 1);
    const int qd  = tid >> 6;                    // channel quarter / segment id

    for (int idx = tid; idx < IN_CHAN * OC; idx += 256) {
        int o = idx & (OC - 1), c = idx >> 5;
        sw[c][o] = w[o * IN_CHAN + c];
    }
    if (tid < OC) {
        float sc = gamma[tid] * rsqrtf(var[tid] + BN_EPS);
        sscale[tid] = sc;
        sbias[tid]  = (bq[tid] - mean[tid]) * sc + beta[tid];
    }
    __syncthreads();

    const int n    = blockIdx.y;
    const int gpix = blockIdx.x * QPIX + p;
    const bool live = (gpix < HW);               // uniform per block (3136 = 49*64)

    float acc[OC];
    #pragma unroll
    for (int o = 0; o < OC; o++) acc[o] = 0.f;

    if (live) {
        const int cbase = qd * 32;
        const float* xp = x + (size_t)n * IN_CHAN * HW + gpix;

        float xv[2][8];
        #pragma unroll
        for (int u = 0; u < 8; u++)
            xv[0][u] = __ldg(xp + (size_t)(cbase + u) * HW);

        #pragma unroll
        for (int cb = 0; cb < 32; cb += 8) {
            const int cur = (cb >> 3) & 1;
            if (cb + 8 < 32) {
                #pragma unroll
                for (int u = 0; u < 8; u++)
                    xv[1 - cur][u] = __ldg(xp + (size_t)(cbase + cb + 8 + u) * HW);
            }
            #pragma unroll
            for (int u = 0; u < 8; u++) {
                const float xs = xv[cur][u];
                const float* swr = &sw[cbase + cb + u][0];
                #pragma unroll
                for (int o = 0; o < OC; o++)
                    acc[o] = fmaf(xs, swr[o], acc[o]);
            }
        }
    }

    // ---- 4 -> 2 -> 1 smem tree reduction across channel quarters ----
    if (qd >= 2) {
        #pragma unroll
        for (int o = 0; o < OC; o++) sacc[qd - 2][p][o] = acc[o];
    }
    __syncthreads();
    if (qd < 2) {
        #pragma unroll
        for (int o = 0; o < OC; o++) acc[o] += sacc[qd][p][o];
        if (qd == 1) {
            #pragma unroll
            for (int o = 0; o < OC; o++) sacc[0][p][o] = acc[o];
        }
    }
    __syncthreads();
    if (qd == 0) {
        #pragma unroll
        for (int o = 0; o < OC; o++) {
            float tot = acc[o] + sacc[0][p][o];
            sr[p][o] = fmaf(tot, sscale[o], sbias[o]);
        }
    }
    __syncthreads();

    // ---- segmented epilogue: seg = qd, each 64-thread group does one array ----
    if (live) {
        if (qd == 0) {               // A[0..7] = q + rk
            float av[8];
            #pragma unroll
            for (int c = 0; c < 8; c++)
                av[c] = sr[p][c] + __ldg(rk + (size_t)c * HW + gpix);
            reinterpret_cast<float4*>(&g_A[n][gpix][0])[0] = reinterpret_cast<float4*>(av)[0];
            reinterpret_cast<float4*>(&g_A[n][gpix][0])[1] = reinterpret_cast<float4*>(av)[1];
        } else if (qd == 1) {        // A[8..15] = rq
            float av[8];
            #pragma unroll
            for (int c = 0; c < 8; c++)
                av[c] = __ldg(rq + (size_t)c * HW + gpix);
            reinterpret_cast<float4*>(&g_A[n][gpix][8])[0] = reinterpret_cast<float4*>(av)[0];
            reinterpret_cast<float4*>(&g_A[n][gpix][8])[1] = reinterpret_cast<float4*>(av)[1];
        } else if (qd == 2) {        // B = [k ; q]
            float bv[16];
            #pragma unroll
            for (int c = 0; c < 8; c++) { bv[c] = sr[p][QC + c]; bv[QC + c] = sr[p][c]; }
            #pragma unroll
            for (int q4 = 0; q4 < 4; q4++)
                reinterpret_cast<float4*>(&g_B[n][gpix][0])[q4] = reinterpret_cast<float4*>(bv)[q4];
        } else {                     // V = v + rv
            float vv[16];
            #pragma unroll
            for (int c = 0; c < 16; c++)
                vv[c] = sr[p][2 * QC + c] + __ldg(rv + (size_t)c * HW + gpix);
            #pragma unroll
            for (int q4 = 0; q4 < 4; q4++)
                reinterpret_cast<float4*>(&g_V[n][gpix][0])[q4] = reinterpret_cast<float4*>(vv)[q4];
        }
    } else {
        float4 z = make_float4(0.f, 0.f, 0.f, 0.f);
        if (qd == 0) {
            reinterpret_cast<float4*>(&g_A[n][gpix][0])[0] = z;
            reinterpret_cast<float4*>(&g_A[n][gpix][0])[1] = z;
        } else if (qd == 1) {
            reinterpret_cast<float4*>(&g_A[n][gpix][8])[0] = z;
            reinterpret_cast<float4*>(&g_A[n][gpix][8])[1] = z;
        } else if (qd == 2) {
            #pragma unroll
            for (int q4 = 0; q4 < 4; q4++)
                reinterpret_cast<float4*>(&g_B[n][gpix][0])[q4] = z;
        } else {
            #pragma unroll
            for (int q4 = 0; q4 < 4; q4++)
                reinterpret_cast<float4*>(&g_V[n][gpix][0])[q4] = z;
        }
    }
}

// ======================================================================
// Kernel 2: attention core (unchanged R3 scalar — at/near FMA-pipe roofline).
// No-max softmax (scores bounded << 88): j-split partials add linearly.
// grid: (13, JSPLIT, NB), block 128; each thread owns 2 queries.
// ======================================================================
__global__ __launch_bounds__(128)
void attn_kernel()
{
    __shared__ __align__(16) float sB[TJ * D];
    __shared__ __align__(16) float sV[TJ * D];

    const int tid   = threadIdx.x;
    const int itile = blockIdx.x;
    const int js    = blockIdx.y;
    const int n     = blockIdx.z;

    const int i0 = itile * 256 + tid;
    const int i1 = i0 + 128;

    float a0[D], a1[D];
    #pragma unroll
    for (int q4 = 0; q4 < 4; q4++) {
        reinterpret_cast<float4*>(a0)[q4] =
            reinterpret_cast<const float4*>(&g_A[n][i0][0])[q4];
        reinterpret_cast<float4*>(a1)[q4] =
            reinterpret_cast<const float4*>(&g_A[n][i1][0])[q4];
    }

    float acc0[D], acc1[D];
    #pragma unroll
    for (int d = 0; d < D; d++) { acc0[d] = 0.f; acc1[d] = 0.f; }
    float l0 = 0.f, l1 = 0.f;

    const int jbase = js * JLEN;
    for (int t = 0; t < JLEN / TJ; t++) {
        const int j0 = jbase + t * TJ;
        reinterpret_cast<float4*>(sB)[tid] =
            reinterpret_cast<const float4*>(&g_B[n][j0][0])[tid];
        reinterpret_cast<float4*>(sV)[tid] =
            reinterpret_cast<const float4*>(&g_V[n][j0][0])[tid];
        __syncthreads();

        #pragma unroll 2
        for (int jj = 0; jj < TJ; jj++) {
            const float* b = &sB[jj * D];
            float s0a = 0.f, s0b = 0.f, s1a = 0.f, s1b = 0.f;
            #pragma unroll
            for (int d = 0; d < D; d += 2) {
                s0a = fmaf(a0[d],     b[d],     s0a);
                s0b = fmaf(a0[d + 1], b[d + 1], s0b);
                s1a = fmaf(a1[d],     b[d],     s1a);
                s1b = fmaf(a1[d + 1], b[d + 1], s1b);
            }
            float p0 = __expf(s0a + s0b);
            float p1 = __expf(s1a + s1b);
            l0 += p0; l1 += p1;
            const float* v = &sV[jj * D];
            #pragma unroll
            for (int d = 0; d < D; d++) {
                acc0[d] = fmaf(p0, v[d], acc0[d]);
                acc1[d] = fmaf(p1, v[d], acc1[d]);
            }
        }
        __syncthreads();
    }

    #pragma unroll
    for (int q4 = 0; q4 < 4; q4++) {
        reinterpret_cast<float4*>(&g_pacc[js][n][i0][0])[q4] =
            reinterpret_cast<float4*>(acc0)[q4];
        reinterpret_cast<float4*>(&g_pacc[js][n][i1][0])[q4] =
            reinterpret_cast<float4*>(acc1)[q4];
    }
    g_pl[js][n][i0] = l0;
    g_pl[js][n][i1] = l1;
}

// ======================================================================
// Kernel 3: combine j-split partials, normalize, 2x2 avg pool.
// ======================================================================
__global__ void combine_kernel(float* __restrict__ out)
{
    const int idx = blockIdx.x * blockDim.x + threadIdx.x;
    const int TOT = NB * 2 * QC * 28 * 28;
    if (idx >= TOT) return;
    int pw = idx % 28;
    int t  = idx / 28;
    int ph = t % 28; t /= 28;
    int c  = t % (2 * QC);
    int n  = t / (2 * QC);

    float r = 0.f;
    #pragma unroll
    for (int sh = 0; sh < 2; sh++) {
        #pragma unroll
        for (int sw_ = 0; sw_ < 2; sw_++) {
            int i = (2 * ph + sh) * 56 + (2 * pw + sw_);
            float num = 0.f, den = 0.f;
            #pragma unroll
            for (int s = 0; s < JSPLIT; s++) {
                num += g_pacc[s][n][i][c];
                den += g_pl[s][n][i];
            }
            r += num / den;
        }
    }
    out[idx] = 0.25f * r;
}

// ======================================================================
extern "C" void kernel_launch(void* const* d_in, const int* in_sizes, int n_in,
                              void* d_out, int out_size)
{
    const float* x     = (const float*)d_in[0];
    const float* w     = (const float*)d_in[1];
    const float* bq    = (const float*)d_in[2];
    const float* gamma = (const float*)d_in[3];
    const float* beta  = (const float*)d_in[4];
    const float* mean  = (const float*)d_in[5];
    const float* var   = (const float*)d_in[6];
    const float* rq    = (const float*)d_in[7];
    const float* rk    = (const float*)d_in[8];
    const float* rv    = (const float*)d_in[9];
    float* out = (float*)d_out;

    dim3 g1(HWP / QPIX, NB);          // (52, 4)
    qkv_kernel<<<g1, 256>>>(x, w, bq, gamma, beta, mean, var, rq, rk, rv);

    dim3 g2(HWP / 256, JSPLIT, NB);   // (13, 14, 4)
    attn_kernel<<<g2, 128>>>();

    const int TOT = NB * 2 * QC * 28 * 28;
    combine_kernel<<<(TOT + 255) / 256, 256>>>(out);
}

// round 7
// speedup vs baseline: 1.4071x; 1.2171x over previous
#include <cuda_runtime.h>
#include <math.h>
#include <stdint.h>

#define NB      4
#define IN_CHAN 128
#define HW      3136
#define HWP     3328      // 26*128 = 13*256 = 52*64
#define OC      32
#define QC      8
#define D       16
#define JSPLIT  14
#define JLEN    (HW / JSPLIT)   // 224
#define TJ      32
#define BN_EPS  1e-5f
#define QPIX    64
#define LOG2E   1.44269504088896340736f

#define SB_STRIDE 20      // 80B rows: float4-aligned, conflict-free B-frag LDS
#define SP_STRIDE 36      // conflict-free AV A-frag LDS (4g+tg distinct)

// ---------------- scratch (device globals; no allocation allowed) ----------------
__device__ __align__(16) float g_A[NB][HWP][D];                 // log2e*[q + rk ; rq]
__device__ __align__(16) float g_B[NB][HWP][D];                 // [k ; q]
__device__ __align__(16) float g_V[NB][HWP][D];                 // v + rv
__device__ __align__(16) float g_pacc[JSPLIT][NB][HWP][D];      // partial sum(e^s * v)
__device__ __align__(16) float g_pl[JSPLIT][NB][HWP];           // partial sum(e^s)

// ---------------- tf32 mma helpers ----------------
__device__ __forceinline__ uint32_t f2tf(float f) {
    uint32_t r; asm("cvt.rna.tf32.f32 %0, %1;" : "=r"(r) : "f"(f)); return r;
}
__device__ __forceinline__ float ex2f(float x) {
    float r; asm("ex2.approx.ftz.f32 %0, %1;" : "=f"(r) : "f"(x)); return r;
}
__device__ __forceinline__ void mma8(float* d, const uint32_t* a, const uint32_t* b) {
    asm("mma.sync.aligned.m16n8k8.row.col.f32.tf32.tf32.f32 "
        "{%0,%1,%2,%3}, {%4,%5,%6,%7}, {%8,%9}, {%0,%1,%2,%3};"
        : "+f"(d[0]), "+f"(d[1]), "+f"(d[2]), "+f"(d[3])
        : "r"(a[0]), "r"(a[1]), "r"(a[2]), "r"(a[3]), "r"(b[0]), "r"(b[1]));
}
// split x into tf32 hi + tf32 lo
__device__ __forceinline__ void tfsplit(float x, uint32_t& hi, uint32_t& lo) {
    hi = f2tf(x);
    lo = f2tf(x - __uint_as_float(hi));
}

// ======================================================================
// Kernel 1: QKV 1x1 conv + BN + build A/B/Vext (A pre-scaled by log2e).
// (R4 structure: 256 thr / 64 pix, 4-way channel split + tree reduce.)
// ======================================================================
__global__ __launch_bounds__(256)
void qkv_kernel(const float* __restrict__ x, const float* __restrict__ w,
                const float* __restrict__ bq, const float* __restrict__ gamma,
                const float* __restrict__ beta, const float* __restrict__ mean,
                const float* __restrict__ var,
                const float* __restrict__ rq, const float* __restrict__ rk,
                const float* __restrict__ rv)
{
    __shared__ float sw[IN_CHAN][OC];
    __shared__ float sscale[OC], sbias[OC];
    __shared__ float sacc[2][QPIX][OC + 1];
    __shared__ float sr[QPIX][OC + 1];

    const int tid = threadIdx.x;
    const int p   = tid & (QPIX - 1);
    const int qd  = tid >> 6;

    for (int idx = tid; idx < IN_CHAN * OC; idx += 256) {
        int o = idx & (OC - 1), c = idx >> 5;
        sw[c][o] = w[o * IN_CHAN + c];
    }
    if (tid < OC) {
        float sc = gamma[tid] * rsqrtf(var[tid] + BN_EPS);
        sscale[tid] = sc;
        sbias[tid]  = (bq[tid] - mean[tid]) * sc + beta[tid];
    }
    __syncthreads();

    const int n    = blockIdx.y;
    const int gpix = blockIdx.x * QPIX + p;
    const bool live = (gpix < HW);

    float acc[OC];
    #pragma unroll
    for (int o = 0; o < OC; o++) acc[o] = 0.f;

    if (live) {
        const int cbase = qd * 32;
        const float* xp = x + (size_t)n * IN_CHAN * HW + gpix;
        float xv[2][8];
        #pragma unroll
        for (int u = 0; u < 8; u++)
            xv[0][u] = __ldg(xp + (size_t)(cbase + u) * HW);
        #pragma unroll
        for (int cb = 0; cb < 32; cb += 8) {
            const int cur = (cb >> 3) & 1;
            if (cb + 8 < 32) {
                #pragma unroll
                for (int u = 0; u < 8; u++)
                    xv[1 - cur][u] = __ldg(xp + (size_t)(cbase + cb + 8 + u) * HW);
            }
            #pragma unroll
            for (int u = 0; u < 8; u++) {
                const float xs = xv[cur][u];
                const float* swr = &sw[cbase + cb + u][0];
                #pragma unroll
                for (int o = 0; o < OC; o++)
                    acc[o] = fmaf(xs, swr[o], acc[o]);
            }
        }
    }

    if (qd >= 2) {
        #pragma unroll
        for (int o = 0; o < OC; o++) sacc[qd - 2][p][o] = acc[o];
    }
    __syncthreads();
    if (qd < 2) {
        #pragma unroll
        for (int o = 0; o < OC; o++) acc[o] += sacc[qd][p][o];
        if (qd == 1) {
            #pragma unroll
            for (int o = 0; o < OC; o++) sacc[0][p][o] = acc[o];
        }
    }
    __syncthreads();
    if (qd == 0) {
        #pragma unroll
        for (int o = 0; o < OC; o++) {
            float tot = acc[o] + sacc[0][p][o];
            sr[p][o] = fmaf(tot, sscale[o], sbias[o]);
        }
    }
    __syncthreads();

    if (live) {
        if (qd == 0) {               // A[0..7] = log2e*(q + rk)
            float av[8];
            #pragma unroll
            for (int c = 0; c < 8; c++)
                av[c] = LOG2E * (sr[p][c] + __ldg(rk + (size_t)c * HW + gpix));
            reinterpret_cast<float4*>(&g_A[n][gpix][0])[0] = reinterpret_cast<float4*>(av)[0];
            reinterpret_cast<float4*>(&g_A[n][gpix][0])[1] = reinterpret_cast<float4*>(av)[1];
        } else if (qd == 1) {        // A[8..15] = log2e*rq
            float av[8];
            #pragma unroll
            for (int c = 0; c < 8; c++)
                av[c] = LOG2E * __ldg(rq + (size_t)c * HW + gpix);
            reinterpret_cast<float4*>(&g_A[n][gpix][8])[0] = reinterpret_cast<float4*>(av)[0];
            reinterpret_cast<float4*>(&g_A[n][gpix][8])[1] = reinterpret_cast<float4*>(av)[1];
        } else if (qd == 2) {        // B = [k ; q]
            float bv[16];
            #pragma unroll
            for (int c = 0; c < 8; c++) { bv[c] = sr[p][QC + c]; bv[QC + c] = sr[p][c]; }
            #pragma unroll
            for (int q4 = 0; q4 < 4; q4++)
                reinterpret_cast<float4*>(&g_B[n][gpix][0])[q4] = reinterpret_cast<float4*>(bv)[q4];
        } else {                     // V = v + rv
            float vv[16];
            #pragma unroll
            for (int c = 0; c < 16; c++)
                vv[c] = sr[p][2 * QC + c] + __ldg(rv + (size_t)c * HW + gpix);
            #pragma unroll
            for (int q4 = 0; q4 < 4; q4++)
                reinterpret_cast<float4*>(&g_V[n][gpix][0])[q4] = reinterpret_cast<float4*>(vv)[q4];
        }
    } else {
        float4 z = make_float4(0.f, 0.f, 0.f, 0.f);
        if (qd == 0) {
            reinterpret_cast<float4*>(&g_A[n][gpix][0])[0] = z;
            reinterpret_cast<float4*>(&g_A[n][gpix][0])[1] = z;
        } else if (qd == 1) {
            reinterpret_cast<float4*>(&g_A[n][gpix][8])[0] = z;
            reinterpret_cast<float4*>(&g_A[n][gpix][8])[1] = z;
        } else if (qd == 2) {
            #pragma unroll
            for (int q4 = 0; q4 < 4; q4++)
                reinterpret_cast<float4*>(&g_B[n][gpix][0])[q4] = z;
        } else {
            #pragma unroll
            for (int q4 = 0; q4 < 4; q4++)
                reinterpret_cast<float4*>(&g_V[n][gpix][0])[q4] = z;
        }
    }
}

// ======================================================================
// Kernel 2: tensor-core attention (tf32x3 both GEMMs).
// Block = 128 thr (4 warps) owns 128 i-rows x one j-split.
// Warp w owns rows [w*32, w*32+32): two m16 groups.
// grid: (HWP/128=26, JSPLIT, NB)
// ======================================================================
__global__ __launch_bounds__(128)
void attn_kernel()
{
    __shared__ __align__(16) float sB[TJ][SB_STRIDE];
    __shared__ __align__(16) float sV[TJ][SB_STRIDE];
    __shared__ float sp[128][SP_STRIDE];

    const int tid   = threadIdx.x;
    const int warp  = tid >> 5;
    const int lane  = tid & 31;
    const int g     = lane >> 2;      // groupID
    const int tg    = lane & 3;       // threadID in group
    const int itile = blockIdx.x;
    const int js    = blockIdx.y;
    const int n     = blockIdx.z;
    const int i0    = itile * 128;
    const int wbase = warp * 32;

    // ---- A fragments (persistent): [mg][ks][reg], hi/lo tf32 ----
    uint32_t ah[2][2][4], al[2][2][4];
    #pragma unroll
    for (int mg = 0; mg < 2; mg++)
        #pragma unroll
        for (int ks = 0; ks < 2; ks++)
            #pragma unroll
            for (int r = 0; r < 4; r++) {
                int row = i0 + wbase + mg * 16 + g + ((r & 1) ? 8 : 0);
                int col = ks * 8 + tg + ((r & 2) ? 4 : 0);
                float af = g_A[n][row][col];            // already *log2e
                tfsplit(af, ah[mg][ks][r], al[mg][ks][r]);
            }

    // ---- persistent AV accumulators and row-sum accumulators ----
    float co[2][2][4];
    #pragma unroll
    for (int mg = 0; mg < 2; mg++)
        #pragma unroll
        for (int nt = 0; nt < 2; nt++)
            #pragma unroll
            for (int r = 0; r < 4; r++) co[mg][nt][r] = 0.f;
    float L[2][2] = {{0.f, 0.f}, {0.f, 0.f}};

    const int jbase = js * JLEN;
    for (int t = 0; t < JLEN / TJ; t++) {
        const int j0 = jbase + t * TJ;
        {   // cooperative tile load: 32 rows x 16 cols each
            int r = tid >> 2, c4 = (tid & 3) * 4;
            *reinterpret_cast<float4*>(&sB[r][c4]) =
                *reinterpret_cast<const float4*>(&g_B[n][j0 + r][c4]);
            *reinterpret_cast<float4*>(&sV[r][c4]) =
                *reinterpret_cast<const float4*>(&g_V[n][j0 + r][c4]);
        }
        __syncthreads();

        // ---- scores: S[32i x 32j] per warp ----
        float cs[2][4][4];
        #pragma unroll
        for (int mg = 0; mg < 2; mg++)
            #pragma unroll
            for (int nt = 0; nt < 4; nt++)
                #pragma unroll
                for (int r = 0; r < 4; r++) cs[mg][nt][r] = 0.f;

        #pragma unroll
        for (int ks = 0; ks < 2; ks++) {
            uint32_t bh[4][2], bl[4][2];
            #pragma unroll
            for (int nt = 0; nt < 4; nt++)
                #pragma unroll
                for (int rr = 0; rr < 2; rr++) {
                    float bf = sB[nt * 8 + g][ks * 8 + tg + rr * 4];
                    tfsplit(bf, bh[nt][rr], bl[nt][rr]);
                }
            #pragma unroll
            for (int mg = 0; mg < 2; mg++)
                #pragma unroll
                for (int nt = 0; nt < 4; nt++) {
                    mma8(cs[mg][nt], ah[mg][ks], bh[nt]);
                    mma8(cs[mg][nt], al[mg][ks], bh[nt]);
                    mma8(cs[mg][nt], ah[mg][ks], bl[nt]);
                }
        }

        // ---- exp2, row sums, stage P to smem ----
        #pragma unroll
        for (int mg = 0; mg < 2; mg++) {
            float s0 = 0.f, s1 = 0.f;
            #pragma unroll
            for (int nt = 0; nt < 4; nt++) {
                float p0 = ex2f(cs[mg][nt][0]);
                float p1 = ex2f(cs[mg][nt][1]);
                float p2 = ex2f(cs[mg][nt][2]);
                float p3 = ex2f(cs[mg][nt][3]);
                s0 += p0 + p1;
                s1 += p2 + p3;
                int r0 = wbase + mg * 16 + g;
                int c  = nt * 8 + 2 * tg;
                *reinterpret_cast<float2*>(&sp[r0][c])     = make_float2(p0, p1);
                *reinterpret_cast<float2*>(&sp[r0 + 8][c]) = make_float2(p2, p3);
            }
            s0 += __shfl_xor_sync(0xffffffffu, s0, 1);
            s0 += __shfl_xor_sync(0xffffffffu, s0, 2);
            s1 += __shfl_xor_sync(0xffffffffu, s1, 1);
            s1 += __shfl_xor_sync(0xffffffffu, s1, 2);
            L[mg][0] += s0;
            L[mg][1] += s1;
        }
        __syncwarp();

        // ---- AV: co += P(32j) x V(32j x 16d) ----
        #pragma unroll
        for (int kj = 0; kj < 4; kj++) {
            uint32_t pah[2][4], pal[2][4];
            #pragma unroll
            for (int mg = 0; mg < 2; mg++)
                #pragma unroll
                for (int r = 0; r < 4; r++) {
                    int row = wbase + mg * 16 + g + ((r & 1) ? 8 : 0);
                    int col = kj * 8 + tg + ((r & 2) ? 4 : 0);
                    tfsplit(sp[row][col], pah[mg][r], pal[mg][r]);
                }
            uint32_t vh[2][2], vl[2][2];
            #pragma unroll
            for (int nt = 0; nt < 2; nt++)
                #pragma unroll
                for (int rr = 0; rr < 2; rr++) {
                    float vf = sV[kj * 8 + tg + rr * 4][nt * 8 + g];
                    tfsplit(vf, vh[nt][rr], vl[nt][rr]);
                }
            #pragma unroll
            for (int mg = 0; mg < 2; mg++)
                #pragma unroll
                for (int nt = 0; nt < 2; nt++) {
                    mma8(co[mg][nt], pah[mg], vh[nt]);
                    mma8(co[mg][nt], pal[mg], vh[nt]);
                    mma8(co[mg][nt], pah[mg], vl[nt]);
                }
        }
        __syncthreads();
    }

    // ---- epilogue: raw accumulators + row sums (combine normalizes) ----
    #pragma unroll
    for (int mg = 0; mg < 2; mg++)
        #pragma unroll
        for (int nt = 0; nt < 2; nt++) {
            int r0 = i0 + wbase + mg * 16 + g;
            int c  = nt * 8 + 2 * tg;
            *reinterpret_cast<float2*>(&g_pacc[js][n][r0][c]) =
                make_float2(co[mg][nt][0], co[mg][nt][1]);
            *reinterpret_cast<float2*>(&g_pacc[js][n][r0 + 8][c]) =
                make_float2(co[mg][nt][2], co[mg][nt][3]);
        }
    if (tg == 0) {
        #pragma unroll
        for (int mg = 0; mg < 2; mg++) {
            g_pl[js][n][i0 + wbase + mg * 16 + g]     = L[mg][0];
            g_pl[js][n][i0 + wbase + mg * 16 + g + 8] = L[mg][1];
        }
    }
}

// ======================================================================
// Kernel 3: combine j-split partials, normalize, 2x2 avg pool.
// ======================================================================
__global__ void combine_kernel(float* __restrict__ out)
{
    const int idx = blockIdx.x * blockDim.x + threadIdx.x;
    const int TOT = NB * 2 * QC * 28 * 28;
    if (idx >= TOT) return;
    int pw = idx % 28;
    int t  = idx / 28;
    int ph = t % 28; t /= 28;
    int c  = t % (2 * QC);
    int n  = t / (2 * QC);

    float r = 0.f;
    #pragma unroll
    for (int sh = 0; sh < 2; sh++) {
        #pragma unroll
        for (int sw_ = 0; sw_ < 2; sw_++) {
            int i = (2 * ph + sh) * 56 + (2 * pw + sw_);
            float num = 0.f, den = 0.f;
            #pragma unroll
            for (int s = 0; s < JSPLIT; s++) {
                num += g_pacc[s][n][i][c];
                den += g_pl[s][n][i];
            }
            r += num / den;
        }
    }
    out[idx] = 0.25f * r;
}

// ======================================================================
extern "C" void kernel_launch(void* const* d_in, const int* in_sizes, int n_in,
                              void* d_out, int out_size)
{
    const float* x     = (const float*)d_in[0];
    const float* w     = (const float*)d_in[1];
    const float* bq    = (const float*)d_in[2];
    const float* gamma = (const float*)d_in[3];
    const float* beta  = (const float*)d_in[4];
    const float* mean  = (const float*)d_in[5];
    const float* var   = (const float*)d_in[6];
    const float* rq    = (const float*)d_in[7];
    const float* rk    = (const float*)d_in[8];
    const float* rv    = (const float*)d_in[9];
    float* out = (float*)d_out;

    dim3 g1(HWP / QPIX, NB);          // (52, 4)
    qkv_kernel<<<g1, 256>>>(x, w, bq, gamma, beta, mean, var, rq, rk, rv);

    dim3 g2(HWP / 128, JSPLIT, NB);   // (26, 14, 4)
    attn_kernel<<<g2, 128>>>();

    const int TOT = NB * 2 * QC * 28 * 28;
    combine_kernel<<<(TOT + 255) / 256, 256>>>(out);
}